// round 14
// baseline (speedup 1.0000x reference)
#include <cuda_runtime.h>
#include <cuda_fp16.h>
#include <math.h>
#include <stdint.h>

#define BATCH 4
#define DIM   512
#define MLEN  4096
#define HEADS 8
#define HD    64
#define KCONV 4608
#define YROWS 4356
#define SMEMB 73728   // 2 stages * (18432 + 18432), BK=64
#define ASMEM 30720   // attn: 3 * (5120 + 5120)

// ---------------- static scratch ----------------
__device__ float  g_part[BATCH*HEADS*8*HD*HD];
__device__ float  g_ns2 [BATCH*2*DIM];
__device__ float  g_attn[BATCH*HEADS*HD*HD];
__device__ __half g_qh  [BATCH*DIM*MLEN];
__device__ __half g_kh  [BATCH*DIM*MLEN];
__device__ __half g_xTh [BATCH*MLEN*DIM];
__device__ __half g_yTh [BATCH*YROWS*DIM];
__device__ __half g_vTh [BATCH*MLEN*DIM];
__device__ __half g_wkvh[2*DIM*DIM];
__device__ __half g_wqTh[DIM*DIM];
__device__ __half g_wdwh[9*DIM*DIM];
__device__ __half g_wc2h[DIM*KCONV];
__device__ __half g_w2h [BATCH*DIM*DIM];

// ---------------- helpers ----------------
__device__ __forceinline__ void cpa16(uint32_t d, const void* s){
    asm volatile("cp.async.cg.shared.global [%0], [%1], 16;" :: "r"(d), "l"(s));
}
#define CP_COMMIT() asm volatile("cp.async.commit_group;")
#define CP_WAIT0()  asm volatile("cp.async.wait_group 0;")
#define CP_WAIT1()  asm volatile("cp.async.wait_group 1;")

__device__ __forceinline__ void mma16(float& c0, float& c1, float& c2, float& c3,
                                      uint32_t a0, uint32_t a1, uint32_t a2, uint32_t a3,
                                      uint32_t b0, uint32_t b1){
    asm volatile(
        "mma.sync.aligned.m16n8k16.row.col.f32.f16.f16.f32 "
        "{%0,%1,%2,%3}, {%4,%5,%6,%7}, {%8,%9}, {%0,%1,%2,%3};"
        : "+f"(c0), "+f"(c1), "+f"(c2), "+f"(c3)
        : "r"(a0), "r"(a1), "r"(a2), "r"(a3), "r"(b0), "r"(b1));
}
__device__ __forceinline__ void ldsm4(uint32_t& r0, uint32_t& r1, uint32_t& r2, uint32_t& r3,
                                      uint32_t a){
    asm volatile("ldmatrix.sync.aligned.m8n8.x4.shared.b16 {%0,%1,%2,%3}, [%4];"
        : "=r"(r0), "=r"(r1), "=r"(r2), "=r"(r3) : "r"(a));
}

// ============ hgemm: 128x128, BK=64, 2-stage, occ 2 ============
// Row stride 144B (64 halves + 16B pad). Stage: A 18432B + B 18432B.
// OUTM: 0 fp32 C; 1 fp16 C; 2 kv-special (bm<512 -> fp16 k; else vT fp16)
template<int CONV, int OUTM>
__global__ __launch_bounds__(256, 2)
void hgemm(const __half* __restrict__ A, long lA,
           const __half* __restrict__ B, long lB,
           void* __restrict__ Cv, long lC, int ldC,
           int M, int K, __half* __restrict__ VT)
{
    extern __shared__ __half sh[];
    const uint32_t smb = (uint32_t)__cvta_generic_to_shared(sh);
    A += (long)blockIdx.z * lA;
    B += (long)blockIdx.z * lB;
    const int bm = blockIdx.y * 128, bn = blockIdx.x * 128;
    const int tid = threadIdx.x, lane = tid & 31, warp = tid >> 5;
    const int wm = (warp >> 2) * 64, wn = (warp & 3) * 32;
    const int g = lane >> 2, t = lane & 3;
    const int lrow = tid >> 1;              // 0..127
    const int lco  = (tid & 1) * 32;        // halves 0 / 32

    int ph = 0, pw = 0;
    if (CONV) { const int n = bn + lrow; ph = n >> 6; pw = n & 63; }

    const uint32_t aOff = (uint32_t)((wm + (lane & 15)) * 144 + (lane >> 4) * 16);
    const uint32_t bOff = 18432u + (uint32_t)((wn + (lane & 7) + ((lane >> 4) << 3)) * 144
                                              + ((lane >> 3) & 1) * 16);

    float acc[4][4][4];
#pragma unroll
    for (int i = 0; i < 4; i++)
#pragma unroll
        for (int j = 0; j < 4; j++)
#pragma unroll
            for (int r = 0; r < 4; r++) acc[i][j][r] = 0.f;

    const int T = K >> 6;

    auto load = [&](int s, int tt){
        const int k0 = tt << 6;
        const uint32_t sb = smb + (uint32_t)s * 36864u;
        const __half* asrc = A + (long)(bm + lrow) * K + k0 + lco;
        const uint32_t adst = sb + (uint32_t)lrow * 144u + (uint32_t)lco * 2u;
#pragma unroll
        for (int i = 0; i < 4; i++)
            cpa16(adst + (uint32_t)i * 16u, asrc + i * 8);
        const __half* bsrc;
        if (CONV) {
            const int r = k0 >> 9;
            const int dyr = r / 3, dxr = r - 3 * dyr;
            bsrc = B + ((long)((ph + dyr) * 66 + pw + dxr)) * DIM + (k0 & 511) + lco;
        } else {
            bsrc = B + (long)(bn + lrow) * K + k0 + lco;
        }
        const uint32_t bdst = sb + 18432u + (uint32_t)lrow * 144u + (uint32_t)lco * 2u;
#pragma unroll
        for (int i = 0; i < 4; i++)
            cpa16(bdst + (uint32_t)i * 16u, bsrc + i * 8);
    };

    load(0, 0); CP_COMMIT();

    for (int tt = 0; tt < T; tt++) {
        const int s = tt & 1;
        CP_WAIT0();
        __syncthreads();
        if (tt + 1 < T) { load(s ^ 1, tt + 1); CP_COMMIT(); }

        const uint32_t sb = smb + (uint32_t)s * 36864u;
#pragma unroll
        for (int ks = 0; ks < 4; ks++) {
            const uint32_t kb = (uint32_t)ks * 32u;
            uint32_t af[4][4], bf[2][4];
#pragma unroll
            for (int mi = 0; mi < 4; mi++)
                ldsm4(af[mi][0], af[mi][1], af[mi][2], af[mi][3],
                      sb + aOff + (uint32_t)mi * 2304u + kb);
            ldsm4(bf[0][0], bf[0][1], bf[0][2], bf[0][3], sb + bOff + kb);
            ldsm4(bf[1][0], bf[1][1], bf[1][2], bf[1][3], sb + bOff + 2304u + kb);
#pragma unroll
            for (int mi = 0; mi < 4; mi++)
#pragma unroll
                for (int ni = 0; ni < 4; ni++) {
                    const int p = ni >> 1, q2 = (ni & 1) * 2;
                    mma16(acc[mi][ni][0], acc[mi][ni][1], acc[mi][ni][2], acc[mi][ni][3],
                          af[mi][0], af[mi][1], af[mi][2], af[mi][3],
                          bf[p][q2], bf[p][q2 + 1]);
                }
        }
    }

    const bool vpath = (OUTM == 2) && (bm >= 512);
    if (OUTM == 1 || (OUTM == 2 && !vpath)) {
        __half* C = (__half*)Cv + (long)blockIdx.z * lC;
#pragma unroll
        for (int mi = 0; mi < 4; mi++) {
            const int row0 = bm + wm + mi * 16 + g;
#pragma unroll
            for (int ni = 0; ni < 4; ni++) {
                const int col = bn + wn + ni * 8 + 2 * t;
                *(__half2*)(C + (long)row0 * ldC + col) =
                    __floats2half2_rn(acc[mi][ni][0], acc[mi][ni][1]);
                *(__half2*)(C + (long)(row0 + 8) * ldC + col) =
                    __floats2half2_rn(acc[mi][ni][2], acc[mi][ni][3]);
            }
        }
    } else if (OUTM == 0) {
        float* C = (float*)Cv + (long)blockIdx.z * lC;
#pragma unroll
        for (int mi = 0; mi < 4; mi++) {
            const int row0 = bm + wm + mi * 16 + g;
#pragma unroll
            for (int ni = 0; ni < 4; ni++) {
                const int col = bn + wn + ni * 8 + 2 * t;
                *(float2*)(C + (long)row0 * ldC + col) =
                    make_float2(acc[mi][ni][0], acc[mi][ni][1]);
                *(float2*)(C + (long)(row0 + 8) * ldC + col) =
                    make_float2(acc[mi][ni][2], acc[mi][ni][3]);
            }
        }
    } else {
        __syncthreads();
#pragma unroll
        for (int mi = 0; mi < 4; mi++) {
            const int r0 = wm + mi * 16 + g;
#pragma unroll
            for (int ni = 0; ni < 4; ni++) {
                const int c0 = wn + ni * 8 + 2 * t;
                sh[(c0    ) * 136 + r0    ] = __float2half_rn(acc[mi][ni][0]);
                sh[(c0 + 1) * 136 + r0    ] = __float2half_rn(acc[mi][ni][1]);
                sh[(c0    ) * 136 + r0 + 8] = __float2half_rn(acc[mi][ni][2]);
                sh[(c0 + 1) * 136 + r0 + 8] = __float2half_rn(acc[mi][ni][3]);
            }
        }
        __syncthreads();
        __half* vt = VT + (long)blockIdx.z * MLEN * DIM;
        const int ml = tid >> 1, ho = (tid & 1) * 64;
        __half* dst = vt + (long)(bn + ml) * DIM + (bm - 512) + ho;
        const __half* srcp = sh + ml * 136 + ho;
#pragma unroll
        for (int i = 0; i < 8; i++)
            *(uint4*)(dst + i * 8) = *(const uint4*)(srcp + i * 8);
    }
}

// ============ attn_mma2: logits on HMMA (R12-validated, 3-stage) ============
__global__ __launch_bounds__(256, 2)
void attn_mma2(const __half* __restrict__ qh, const __half* __restrict__ kh,
               float* __restrict__ part)
{
    extern __shared__ __half sh[];
    const uint32_t smb = (uint32_t)__cvta_generic_to_shared(sh);
    const int mc = blockIdx.x, h = blockIdx.y, b = blockIdx.z;
    const __half* Qp = qh + ((long)(b * DIM + h * HD)) * MLEN + mc * 512;
    const __half* Kp = kh + ((long)(b * DIM + h * HD)) * MLEN + mc * 512;
    const int tid = threadIdx.x, lane = tid & 31, warp = tid >> 5;
    const int wm = (warp >> 1) * 16, wn = (warp & 1) * 32;
    const int g = lane >> 2, t = lane & 3;
    const int lrow = tid >> 2, lco = (tid & 3) * 8;

    const uint32_t aOff = (uint32_t)((wm + (lane & 15)) * 80 + (lane >> 4) * 16);
    const uint32_t bOff = 5120u + (uint32_t)((wn + (lane & 7) + ((lane >> 4) << 3)) * 80
                                             + ((lane >> 3) & 1) * 16);

    float acc[4][4];
#pragma unroll
    for (int j = 0; j < 4; j++)
#pragma unroll
        for (int r = 0; r < 4; r++) acc[j][r] = 0.f;

    const int T = 16;

    auto load = [&](int s, int tt){
        const int k0 = tt << 5;
        const uint32_t sb = smb + (uint32_t)s * 10240u;
        cpa16(sb + (uint32_t)lrow * 80u + (uint32_t)lco * 2u,
              Qp + (long)lrow * MLEN + k0 + lco);
        cpa16(sb + 5120u + (uint32_t)lrow * 80u + (uint32_t)lco * 2u,
              Kp + (long)lrow * MLEN + k0 + lco);
    };

    load(0, 0); CP_COMMIT();
    load(1, 1); CP_COMMIT();

    for (int tt = 0; tt < T; tt++) {
        const int s = tt % 3;
        CP_WAIT1();
        __syncthreads();
        if (tt + 2 < T) load((tt + 2) % 3, tt + 2);
        CP_COMMIT();

        const uint32_t sb = smb + (uint32_t)s * 10240u;
#pragma unroll
        for (int ks = 0; ks < 2; ks++) {
            const uint32_t kb = (uint32_t)ks * 32u;
            uint32_t af[4], bf[2][4];
            ldsm4(af[0], af[1], af[2], af[3], sb + aOff + kb);
            ldsm4(bf[0][0], bf[0][1], bf[0][2], bf[0][3], sb + bOff + kb);
            ldsm4(bf[1][0], bf[1][1], bf[1][2], bf[1][3], sb + bOff + 1280u + kb);
#pragma unroll
            for (int ni = 0; ni < 4; ni++) {
                const int p = ni >> 1, q2 = (ni & 1) * 2;
                mma16(acc[ni][0], acc[ni][1], acc[ni][2], acc[ni][3],
                      af[0], af[1], af[2], af[3],
                      bf[p][q2], bf[p][q2 + 1]);
            }
        }
    }

    float* pp = part + (((long)(b * HEADS + h)) * 8 + mc) * 4096;
    const int row0 = wm + g;
#pragma unroll
    for (int ni = 0; ni < 4; ni++) {
        const int col = wn + ni * 8 + 2 * t;
        *(float2*)(pp + row0 * 64 + col)       = make_float2(acc[ni][0], acc[ni][1]);
        *(float2*)(pp + (row0 + 8) * 64 + col) = make_float2(acc[ni][2], acc[ni][3]);
    }
}

// ============ row sumsq over fp16 q/k ============
__global__ void nsq_kernel(const __half* __restrict__ qh, const __half* __restrict__ kh,
                           float* __restrict__ ns2)
{
    const int w = threadIdx.x >> 5, lane = threadIdx.x & 31;
    const int gid = blockIdx.x * 8 + w;
    const int isK = gid >= BATCH * DIM;
    const int r = gid & (BATCH * DIM - 1);
    const int b = r >> 9, o = r & 511;
    const __half* src = (isK ? kh : qh) + ((long)(b * DIM + o)) * MLEN;
    float ss = 0.f;
#pragma unroll
    for (int i = 0; i < 16; i++) {
        uint4 v = *(const uint4*)(src + i * 256 + lane * 8);
        const __half2* h2 = (const __half2*)&v;
#pragma unroll
        for (int j = 0; j < 4; j++) {
            float2 f = __half22float2(h2[j]);
            ss += f.x * f.x + f.y * f.y;
        }
    }
#pragma unroll
    for (int o2 = 16; o2; o2 >>= 1) ss += __shfl_xor_sync(~0u, ss, o2);
    if (lane == 0) ns2[b * 1024 + isK * 512 + o] = ss;
}

// ---------------- prep / transpose kernels ----------------
__global__ void conv_h(const float* __restrict__ s, __half* __restrict__ d, int n){
    const int i = blockIdx.x * 256 + threadIdx.x;
    if (i < n) d[i] = __float2half_rn(s[i]);
}

template<int PADY>
__global__ void transpose_h(const float* __restrict__ S, long lS,
                            __half* __restrict__ D, long lD, int R, int C)
{
    __shared__ float tle[32][33];
    S += (long)blockIdx.z * lS;
    D += (long)blockIdx.z * lD;
    const int m0 = blockIdx.x * 32, c0 = blockIdx.y * 32;
    const int tx = threadIdx.x & 31, ty = threadIdx.x >> 5;
#pragma unroll
    for (int i = ty; i < 32; i += 8)
        tle[i][tx] = S[(long)(c0 + i) * C + m0 + tx];
    __syncthreads();
    const long prow = PADY ? (long)(m0 + 2 * (m0 >> 6) + 67) : (long)m0;
#pragma unroll
    for (int i = ty; i < 32; i += 8)
        D[(prow + i) * R + c0 + tx] = __float2half_rn(tle[tx][i]);
}

__global__ void ypad_zero_h(__half* __restrict__ yT)
{
    const int idx = blockIdx.x;
    int row;
    if (idx < 66) row = idx;
    else if (idx < 132) row = 65 * 66 + (idx - 66);
    else { const int i = idx - 132; row = (1 + (i >> 1)) * 66 + (i & 1) * 65; }
    uint32_t* p = (uint32_t*)(yT + ((long)blockIdx.y * YROWS + row) * DIM);
    p[threadIdx.x] = 0u;
}

__global__ void prep_wdw_h(const float* __restrict__ wdw, __half* __restrict__ wdwh)
{
    __shared__ float s[KCONV];
    const int o2 = blockIdx.x;
    const float* src = wdw + (long)o2 * KCONV;
    for (int i = threadIdx.x; i < KCONV; i += 256) s[i] = src[i];
    __syncthreads();
    for (int i = threadIdx.x; i < KCONV; i += 256) {
        const int r = i >> 9, o = i & 511;
        wdwh[((long)r * DIM + o2) * DIM + o] = __float2half_rn(s[o * 9 + r]);
    }
}

__global__ void softmax_kernel(const float* __restrict__ part, const float* __restrict__ ns2,
                               const float* __restrict__ temp, float* __restrict__ attn)
{
    const int row = blockIdx.x;
    const int b = row >> 9, h = (row >> 6) & 7, c = row & 63;
    const int lane = threadIdx.x;
    const float sqs = ns2[b * 1024 + h * HD + c];
    const float sk0 = ns2[b * 1024 + 512 + h * HD + lane];
    const float sk1 = ns2[b * 1024 + 512 + h * HD + lane + 32];
    const float rq  = 1.f / fmaxf(sqrtf(sqs), 1e-12f);
    const float rk0 = 1.f / fmaxf(sqrtf(sk0), 1e-12f);
    const float rk1 = 1.f / fmaxf(sqrtf(sk1), 1e-12f);
    const float tq = rq * temp[h];
    const long base = (((long)(b*HEADS + h)) * 8) * (HD*HD) + c*HD;
    float s0 = 0.f, s1 = 0.f;
#pragma unroll
    for (int mc = 0; mc < 8; mc++) {
        s0 += part[base + (long)mc*(HD*HD) + lane];
        s1 += part[base + (long)mc*(HD*HD) + lane + 32];
    }
    float v0 = s0 * tq * rk0, v1 = s1 * tq * rk1;
    float mx = fmaxf(v0, v1);
#pragma unroll
    for (int o = 16; o; o >>= 1) mx = fmaxf(mx, __shfl_xor_sync(~0u, mx, o));
    const float e0 = expf(v0 - mx), e1 = expf(v1 - mx);
    float s = e0 + e1;
#pragma unroll
    for (int o = 16; o; o >>= 1) s += __shfl_xor_sync(~0u, s, o);
    const float inv = 1.f / s;
    float* ap = attn + (((long)(b*HEADS + h))*HD + c)*HD;
    ap[lane] = e0 * inv;
    ap[lane + 32] = e1 * inv;
}

__global__ void w2_kernel_h(const float* __restrict__ w_out, const float* __restrict__ attn,
                            __half* __restrict__ W2h)
{
    const int b = blockIdx.z, h = blockIdx.y;
    const int tid = threadIdx.x;
    __shared__ float sa[HD*HD];
    const float* ap = attn + ((long)(b*HEADS + h)) * HD * HD;
    for (int i = tid; i < HD*HD; i += 256) sa[i] = ap[i];
    __syncthreads();
    const int o = blockIdx.x * 4 + (tid >> 6);
    const int d = tid & 63;
    const float* wrow = w_out + (long)o * DIM + h * HD;
    float acc = 0.f;
#pragma unroll
    for (int c = 0; c < HD; c++) acc += wrow[c] * sa[c*HD + d];
    W2h[((long)b*DIM + o) * DIM + h*HD + d] = __float2half_rn(acc);
}

// ---------------- launcher ----------------
extern "C" void kernel_launch(void* const* d_in, const int* in_sizes, int n_in,
                              void* d_out, int out_size)
{
    const float* x    = (const float*)d_in[0];
    const float* y    = (const float*)d_in[1];
    const float* temp = (const float*)d_in[2];
    const float* wkv  = (const float*)d_in[3];
    const float* wq   = (const float*)d_in[4];
    const float* wdw  = (const float*)d_in[5];
    const float* wout = (const float*)d_in[6];
    float* out = (float*)d_out;

    float *part, *ns2, *attn;
    __half *qh, *kh, *xTh, *yTh, *vTh, *wkvh, *wqTh, *wdwh, *wc2h, *w2h;
    cudaGetSymbolAddress((void**)&part, g_part);
    cudaGetSymbolAddress((void**)&ns2,  g_ns2);
    cudaGetSymbolAddress((void**)&attn, g_attn);
    cudaGetSymbolAddress((void**)&qh,   g_qh);
    cudaGetSymbolAddress((void**)&kh,   g_kh);
    cudaGetSymbolAddress((void**)&xTh,  g_xTh);
    cudaGetSymbolAddress((void**)&yTh,  g_yTh);
    cudaGetSymbolAddress((void**)&vTh,  g_vTh);
    cudaGetSymbolAddress((void**)&wkvh, g_wkvh);
    cudaGetSymbolAddress((void**)&wqTh, g_wqTh);
    cudaGetSymbolAddress((void**)&wdwh, g_wdwh);
    cudaGetSymbolAddress((void**)&wc2h, g_wc2h);
    cudaGetSymbolAddress((void**)&w2h,  g_w2h);

    cudaFuncSetAttribute(hgemm<0,0>, cudaFuncAttributeMaxDynamicSharedMemorySize, SMEMB);
    cudaFuncSetAttribute(hgemm<0,1>, cudaFuncAttributeMaxDynamicSharedMemorySize, SMEMB);
    cudaFuncSetAttribute(hgemm<0,2>, cudaFuncAttributeMaxDynamicSharedMemorySize, SMEMB);
    cudaFuncSetAttribute(hgemm<1,1>, cudaFuncAttributeMaxDynamicSharedMemorySize, SMEMB);
    cudaFuncSetAttribute(attn_mma2, cudaFuncAttributeMaxDynamicSharedMemorySize, ASMEM);

    // ---- kv hgemm kept at launch #4 (the slot ncu captures) ----
    transpose_h<0><<<dim3(128,16,BATCH), 256>>>(x, (long)DIM*MLEN, xTh,
                                                (long)MLEN*DIM, DIM, MLEN);    // 1
    conv_h<<<2048, 256>>>(wkv, wkvh, 2*DIM*DIM);                               // 2
    prep_wdw_h<<<512, 256>>>(wdw, wdwh);                                       // 3
    hgemm<0,2><<<dim3(32,8,BATCH), 256, SMEMB>>>(
        wkvh, 0L, xTh, (long)MLEN*DIM, kh, (long)DIM*MLEN, MLEN,
        2*DIM, DIM, vTh);                                                      // 4 <- profiled
    transpose_h<0><<<dim3(16,16,1), 256>>>(wq, 0L, wqTh, 0L, DIM, DIM);        // 5
    ypad_zero_h<<<dim3(260,BATCH), 256>>>(yTh);                                // 6
    transpose_h<1><<<dim3(128,16,BATCH), 256>>>(y, (long)DIM*MLEN, yTh,
                                                (long)YROWS*DIM, DIM, MLEN);   // 7
    hgemm<0,1><<<dim3(4,4,9), 256, SMEMB>>>(
        wdwh, (long)DIM*DIM, wqTh, 0L, wc2h, 512L, KCONV, DIM, DIM, nullptr);  // 8
    hgemm<1,1><<<dim3(32,4,BATCH), 256, SMEMB>>>(
        wc2h, 0L, yTh, (long)YROWS*DIM, qh, (long)DIM*MLEN, MLEN,
        DIM, KCONV, nullptr);                                                  // 9
    nsq_kernel<<<512, 256>>>(qh, kh, ns2);                                     // 10
    attn_mma2<<<dim3(8,HEADS,BATCH), 256, ASMEM>>>(qh, kh, part);              // 11
    softmax_kernel<<<BATCH*HEADS*HD, 32>>>(part, ns2, temp, attn);             // 12
    w2_kernel_h<<<dim3(128,HEADS,BATCH), 256>>>(wout, attn, w2h);              // 13
    hgemm<0,0><<<dim3(32,4,BATCH), 256, SMEMB>>>(
        w2h, (long)DIM*DIM, vTh, (long)MLEN*DIM, out, (long)DIM*MLEN, MLEN,
        DIM, DIM, nullptr);                                                    // 14
}

// round 16
// speedup vs baseline: 1.1570x; 1.1570x over previous
#include <cuda_runtime.h>
#include <cuda_fp16.h>
#include <math.h>
#include <stdint.h>

#define BATCH 4
#define DIM   512
#define MLEN  4096
#define HEADS 8
#define HD    64
#define KCONV 4608
#define YROWS 4356
#define SMEMB 61440   // 3 * (10240 + 10240)
#define ASMEM 30720   // attn: 3 * (5120 + 5120)

// ---------------- static scratch ----------------
__device__ float  g_part[BATCH*HEADS*8*HD*HD];
__device__ float  g_ns2 [BATCH*2*DIM];
__device__ float  g_attn[BATCH*HEADS*HD*HD];
__device__ __half g_qh  [BATCH*DIM*MLEN];
__device__ __half g_kh  [BATCH*DIM*MLEN];
__device__ __half g_xTh [BATCH*MLEN*DIM];
__device__ __half g_yTh [BATCH*YROWS*DIM];
__device__ __half g_vTh [BATCH*MLEN*DIM];
__device__ __half g_wkvh[2*DIM*DIM];
__device__ __half g_wqTh[DIM*DIM];
__device__ __half g_wdwh[9*DIM*DIM];
__device__ __half g_wc2h[DIM*KCONV];
__device__ __half g_w2h [BATCH*DIM*DIM];

// ---------------- helpers ----------------
__device__ __forceinline__ void cpa16(uint32_t d, const void* s){
    asm volatile("cp.async.cg.shared.global [%0], [%1], 16;" :: "r"(d), "l"(s));
}
#define CP_COMMIT() asm volatile("cp.async.commit_group;")
#define CP_WAIT1()  asm volatile("cp.async.wait_group 1;")

__device__ __forceinline__ void mma16(float& c0, float& c1, float& c2, float& c3,
                                      uint32_t a0, uint32_t a1, uint32_t a2, uint32_t a3,
                                      uint32_t b0, uint32_t b1){
    asm volatile(
        "mma.sync.aligned.m16n8k16.row.col.f32.f16.f16.f32 "
        "{%0,%1,%2,%3}, {%4,%5,%6,%7}, {%8,%9}, {%0,%1,%2,%3};"
        : "+f"(c0), "+f"(c1), "+f"(c2), "+f"(c3)
        : "r"(a0), "r"(a1), "r"(a2), "r"(a3), "r"(b0), "r"(b1));
}
__device__ __forceinline__ void ldsm4(uint32_t& r0, uint32_t& r1, uint32_t& r2, uint32_t& r3,
                                      uint32_t a){
    asm volatile("ldmatrix.sync.aligned.m8n8.x4.shared.b16 {%0,%1,%2,%3}, [%4];"
        : "=r"(r0), "=r"(r1), "=r"(r2), "=r"(r3) : "r"(a));
}

// ============ hgemm: 128x128, BK=32, 3-stage, occ 2 (R12-validated) ========
// OUTM: 0 fp32 C; 1 fp16 C; 2 kv-special (bm<512 -> fp16 k; else vT fp16)
template<int CONV, int OUTM>
__global__ __launch_bounds__(256, 2)
void hgemm(const __half* __restrict__ A, long lA,
           const __half* __restrict__ B, long lB,
           void* __restrict__ Cv, long lC, int ldC,
           int M, int K, __half* __restrict__ VT)
{
    extern __shared__ __half sh[];
    const uint32_t smb = (uint32_t)__cvta_generic_to_shared(sh);
    A += (long)blockIdx.z * lA;
    B += (long)blockIdx.z * lB;
    const int bm = blockIdx.y * 128, bn = blockIdx.x * 128;
    const int tid = threadIdx.x, lane = tid & 31, warp = tid >> 5;
    const int wm = (warp >> 2) * 64, wn = (warp & 3) * 32;
    const int g = lane >> 2, t = lane & 3;
    const int lrow = tid >> 1, lco = (tid & 1) * 16;

    int ph = 0, pw = 0;
    if (CONV) { const int n = bn + lrow; ph = n >> 6; pw = n & 63; }

    const uint32_t aOff = (uint32_t)((wm + (lane & 15)) * 80 + (lane >> 4) * 16);
    const uint32_t bOff = 10240u + (uint32_t)((wn + (lane & 7) + ((lane >> 4) << 3)) * 80
                                              + ((lane >> 3) & 1) * 16);

    float acc[4][4][4];
#pragma unroll
    for (int i = 0; i < 4; i++)
#pragma unroll
        for (int j = 0; j < 4; j++)
#pragma unroll
            for (int r = 0; r < 4; r++) acc[i][j][r] = 0.f;

    const int T = K >> 5;

    auto load = [&](int s, int tt){
        const int k0 = tt << 5;
        const uint32_t sb = smb + (uint32_t)s * 20480u;
        const __half* asrc = A + (long)(bm + lrow) * K + k0 + lco;
        const uint32_t adst = sb + (uint32_t)lrow * 80u + (uint32_t)lco * 2u;
        cpa16(adst,       asrc);
        cpa16(adst + 16u, asrc + 8);
        const __half* bsrc;
        if (CONV) {
            const int r = k0 >> 9;
            const int dyr = r / 3, dxr = r - 3 * dyr;
            bsrc = B + ((long)((ph + dyr) * 66 + pw + dxr)) * DIM + (k0 & 511) + lco;
        } else {
            bsrc = B + (long)(bn + lrow) * K + k0 + lco;
        }
        const uint32_t bdst = sb + 10240u + (uint32_t)lrow * 80u + (uint32_t)lco * 2u;
        cpa16(bdst,       bsrc);
        cpa16(bdst + 16u, bsrc + 8);
    };

    load(0, 0); CP_COMMIT();
    load(1, 1); CP_COMMIT();

    for (int tt = 0; tt < T; tt++) {
        const int s = tt % 3;
        CP_WAIT1();
        __syncthreads();
        if (tt + 2 < T) load((tt + 2) % 3, tt + 2);
        CP_COMMIT();

        const uint32_t sb = smb + (uint32_t)s * 20480u;
#pragma unroll
        for (int ks = 0; ks < 2; ks++) {
            const uint32_t kb = (uint32_t)ks * 32u;
            uint32_t af[4][4], bf[2][4];
            // B frags first: every MMA needs them; shortens first-MMA readiness
            ldsm4(bf[0][0], bf[0][1], bf[0][2], bf[0][3], sb + bOff + kb);
            ldsm4(bf[1][0], bf[1][1], bf[1][2], bf[1][3], sb + bOff + 1280u + kb);
#pragma unroll
            for (int mi = 0; mi < 4; mi++)
                ldsm4(af[mi][0], af[mi][1], af[mi][2], af[mi][3],
                      sb + aOff + (uint32_t)mi * 1280u + kb);
#pragma unroll
            for (int mi = 0; mi < 4; mi++)
#pragma unroll
                for (int ni = 0; ni < 4; ni++) {
                    const int p = ni >> 1, q2 = (ni & 1) * 2;
                    mma16(acc[mi][ni][0], acc[mi][ni][1], acc[mi][ni][2], acc[mi][ni][3],
                          af[mi][0], af[mi][1], af[mi][2], af[mi][3],
                          bf[p][q2], bf[p][q2 + 1]);
                }
        }
    }

    const bool vpath = (OUTM == 2) && (bm >= 512);
    if (OUTM == 1 || (OUTM == 2 && !vpath)) {
        __half* C = (__half*)Cv + (long)blockIdx.z * lC;
#pragma unroll
        for (int mi = 0; mi < 4; mi++) {
            const int row0 = bm + wm + mi * 16 + g;
#pragma unroll
            for (int ni = 0; ni < 4; ni++) {
                const int col = bn + wn + ni * 8 + 2 * t;
                *(__half2*)(C + (long)row0 * ldC + col) =
                    __floats2half2_rn(acc[mi][ni][0], acc[mi][ni][1]);
                *(__half2*)(C + (long)(row0 + 8) * ldC + col) =
                    __floats2half2_rn(acc[mi][ni][2], acc[mi][ni][3]);
            }
        }
    } else if (OUTM == 0) {
        float* C = (float*)Cv + (long)blockIdx.z * lC;
#pragma unroll
        for (int mi = 0; mi < 4; mi++) {
            const int row0 = bm + wm + mi * 16 + g;
#pragma unroll
            for (int ni = 0; ni < 4; ni++) {
                const int col = bn + wn + ni * 8 + 2 * t;
                *(float2*)(C + (long)row0 * ldC + col) =
                    make_float2(acc[mi][ni][0], acc[mi][ni][1]);
                *(float2*)(C + (long)(row0 + 8) * ldC + col) =
                    make_float2(acc[mi][ni][2], acc[mi][ni][3]);
            }
        }
    } else {
        __syncthreads();
#pragma unroll
        for (int mi = 0; mi < 4; mi++) {
            const int r0 = wm + mi * 16 + g;
#pragma unroll
            for (int ni = 0; ni < 4; ni++) {
                const int c0 = wn + ni * 8 + 2 * t;
                sh[(c0    ) * 136 + r0    ] = __float2half_rn(acc[mi][ni][0]);
                sh[(c0 + 1) * 136 + r0    ] = __float2half_rn(acc[mi][ni][1]);
                sh[(c0    ) * 136 + r0 + 8] = __float2half_rn(acc[mi][ni][2]);
                sh[(c0 + 1) * 136 + r0 + 8] = __float2half_rn(acc[mi][ni][3]);
            }
        }
        __syncthreads();
        __half* vt = VT + (long)blockIdx.z * MLEN * DIM;
        const int ml = tid >> 1, ho = (tid & 1) * 64;
        __half* dst = vt + (long)(bn + ml) * DIM + (bm - 512) + ho;
        const __half* srcp = sh + ml * 136 + ho;
#pragma unroll
        for (int i = 0; i < 8; i++)
            *(uint4*)(dst + i * 8) = *(const uint4*)(srcp + i * 8);
    }
}

// ============ attn_mma2: logits on HMMA (R12-validated, 3-stage) ============
__global__ __launch_bounds__(256, 2)
void attn_mma2(const __half* __restrict__ qh, const __half* __restrict__ kh,
               float* __restrict__ part)
{
    extern __shared__ __half sh[];
    const uint32_t smb = (uint32_t)__cvta_generic_to_shared(sh);
    const int mc = blockIdx.x, h = blockIdx.y, b = blockIdx.z;
    const __half* Qp = qh + ((long)(b * DIM + h * HD)) * MLEN + mc * 512;
    const __half* Kp = kh + ((long)(b * DIM + h * HD)) * MLEN + mc * 512;
    const int tid = threadIdx.x, lane = tid & 31, warp = tid >> 5;
    const int wm = (warp >> 1) * 16, wn = (warp & 1) * 32;
    const int g = lane >> 2, t = lane & 3;
    const int lrow = tid >> 2, lco = (tid & 3) * 8;

    const uint32_t aOff = (uint32_t)((wm + (lane & 15)) * 80 + (lane >> 4) * 16);
    const uint32_t bOff = 5120u + (uint32_t)((wn + (lane & 7) + ((lane >> 4) << 3)) * 80
                                             + ((lane >> 3) & 1) * 16);

    float acc[4][4];
#pragma unroll
    for (int j = 0; j < 4; j++)
#pragma unroll
        for (int r = 0; r < 4; r++) acc[j][r] = 0.f;

    const int T = 16;

    auto load = [&](int s, int tt){
        const int k0 = tt << 5;
        const uint32_t sb = smb + (uint32_t)s * 10240u;
        cpa16(sb + (uint32_t)lrow * 80u + (uint32_t)lco * 2u,
              Qp + (long)lrow * MLEN + k0 + lco);
        cpa16(sb + 5120u + (uint32_t)lrow * 80u + (uint32_t)lco * 2u,
              Kp + (long)lrow * MLEN + k0 + lco);
    };

    load(0, 0); CP_COMMIT();
    load(1, 1); CP_COMMIT();

    for (int tt = 0; tt < T; tt++) {
        const int s = tt % 3;
        CP_WAIT1();
        __syncthreads();
        if (tt + 2 < T) load((tt + 2) % 3, tt + 2);
        CP_COMMIT();

        const uint32_t sb = smb + (uint32_t)s * 10240u;
#pragma unroll
        for (int ks = 0; ks < 2; ks++) {
            const uint32_t kb = (uint32_t)ks * 32u;
            uint32_t af[4], bf[2][4];
            ldsm4(bf[0][0], bf[0][1], bf[0][2], bf[0][3], sb + bOff + kb);
            ldsm4(bf[1][0], bf[1][1], bf[1][2], bf[1][3], sb + bOff + 1280u + kb);
            ldsm4(af[0], af[1], af[2], af[3], sb + aOff + kb);
#pragma unroll
            for (int ni = 0; ni < 4; ni++) {
                const int p = ni >> 1, q2 = (ni & 1) * 2;
                mma16(acc[ni][0], acc[ni][1], acc[ni][2], acc[ni][3],
                      af[0], af[1], af[2], af[3],
                      bf[p][q2], bf[p][q2 + 1]);
            }
        }
    }

    float* pp = part + (((long)(b * HEADS + h)) * 8 + mc) * 4096;
    const int row0 = wm + g;
#pragma unroll
    for (int ni = 0; ni < 4; ni++) {
        const int col = wn + ni * 8 + 2 * t;
        *(float2*)(pp + row0 * 64 + col)       = make_float2(acc[ni][0], acc[ni][1]);
        *(float2*)(pp + (row0 + 8) * 64 + col) = make_float2(acc[ni][2], acc[ni][3]);
    }
}

// ============ row sumsq over fp16 q/k ============
__global__ void nsq_kernel(const __half* __restrict__ qh, const __half* __restrict__ kh,
                           float* __restrict__ ns2)
{
    const int w = threadIdx.x >> 5, lane = threadIdx.x & 31;
    const int gid = blockIdx.x * 8 + w;
    const int isK = gid >= BATCH * DIM;
    const int r = gid & (BATCH * DIM - 1);
    const int b = r >> 9, o = r & 511;
    const __half* src = (isK ? kh : qh) + ((long)(b * DIM + o)) * MLEN;
    float ss = 0.f;
#pragma unroll
    for (int i = 0; i < 16; i++) {
        uint4 v = *(const uint4*)(src + i * 256 + lane * 8);
        const __half2* h2 = (const __half2*)&v;
#pragma unroll
        for (int j = 0; j < 4; j++) {
            float2 f = __half22float2(h2[j]);
            ss += f.x * f.x + f.y * f.y;
        }
    }
#pragma unroll
    for (int o2 = 16; o2; o2 >>= 1) ss += __shfl_xor_sync(~0u, ss, o2);
    if (lane == 0) ns2[b * 1024 + isK * 512 + o] = ss;
}

// ---------------- prep / transpose kernels ----------------
__global__ void conv_h(const float* __restrict__ s, __half* __restrict__ d, int n){
    const int i = blockIdx.x * 256 + threadIdx.x;
    if (i < n) d[i] = __float2half_rn(s[i]);
}

template<int PADY>
__global__ void transpose_h(const float* __restrict__ S, long lS,
                            __half* __restrict__ D, long lD, int R, int C)
{
    __shared__ float tle[32][33];
    S += (long)blockIdx.z * lS;
    D += (long)blockIdx.z * lD;
    const int m0 = blockIdx.x * 32, c0 = blockIdx.y * 32;
    const int tx = threadIdx.x & 31, ty = threadIdx.x >> 5;
#pragma unroll
    for (int i = ty; i < 32; i += 8)
        tle[i][tx] = S[(long)(c0 + i) * C + m0 + tx];
    __syncthreads();
    const long prow = PADY ? (long)(m0 + 2 * (m0 >> 6) + 67) : (long)m0;
#pragma unroll
    for (int i = ty; i < 32; i += 8)
        D[(prow + i) * R + c0 + tx] = __float2half_rn(tle[tx][i]);
}

__global__ void ypad_zero_h(__half* __restrict__ yT)
{
    const int idx = blockIdx.x;
    int row;
    if (idx < 66) row = idx;
    else if (idx < 132) row = 65 * 66 + (idx - 66);
    else { const int i = idx - 132; row = (1 + (i >> 1)) * 66 + (i & 1) * 65; }
    uint32_t* p = (uint32_t*)(yT + ((long)blockIdx.y * YROWS + row) * DIM);
    p[threadIdx.x] = 0u;
}

__global__ void prep_wdw_h(const float* __restrict__ wdw, __half* __restrict__ wdwh)
{
    __shared__ float s[KCONV];
    const int o2 = blockIdx.x;
    const float* src = wdw + (long)o2 * KCONV;
    for (int i = threadIdx.x; i < KCONV; i += 256) s[i] = src[i];
    __syncthreads();
    for (int i = threadIdx.x; i < KCONV; i += 256) {
        const int r = i >> 9, o = i & 511;
        wdwh[((long)r * DIM + o2) * DIM + o] = __float2half_rn(s[o * 9 + r]);
    }
}

__global__ void softmax_kernel(const float* __restrict__ part, const float* __restrict__ ns2,
                               const float* __restrict__ temp, float* __restrict__ attn)
{
    const int row = blockIdx.x;
    const int b = row >> 9, h = (row >> 6) & 7, c = row & 63;
    const int lane = threadIdx.x;
    const float sqs = ns2[b * 1024 + h * HD + c];
    const float sk0 = ns2[b * 1024 + 512 + h * HD + lane];
    const float sk1 = ns2[b * 1024 + 512 + h * HD + lane + 32];
    const float rq  = 1.f / fmaxf(sqrtf(sqs), 1e-12f);
    const float rk0 = 1.f / fmaxf(sqrtf(sk0), 1e-12f);
    const float rk1 = 1.f / fmaxf(sqrtf(sk1), 1e-12f);
    const float tq = rq * temp[h];
    const long base = (((long)(b*HEADS + h)) * 8) * (HD*HD) + c*HD;
    float s0 = 0.f, s1 = 0.f;
#pragma unroll
    for (int mc = 0; mc < 8; mc++) {
        s0 += part[base + (long)mc*(HD*HD) + lane];
        s1 += part[base + (long)mc*(HD*HD) + lane + 32];
    }
    float v0 = s0 * tq * rk0, v1 = s1 * tq * rk1;
    float mx = fmaxf(v0, v1);
#pragma unroll
    for (int o = 16; o; o >>= 1) mx = fmaxf(mx, __shfl_xor_sync(~0u, mx, o));
    const float e0 = expf(v0 - mx), e1 = expf(v1 - mx);
    float s = e0 + e1;
#pragma unroll
    for (int o = 16; o; o >>= 1) s += __shfl_xor_sync(~0u, s, o);
    const float inv = 1.f / s;
    float* ap = attn + (((long)(b*HEADS + h))*HD + c)*HD;
    ap[lane] = e0 * inv;
    ap[lane + 32] = e1 * inv;
}

__global__ void w2_kernel_h(const float* __restrict__ w_out, const float* __restrict__ attn,
                            __half* __restrict__ W2h)
{
    const int b = blockIdx.z, h = blockIdx.y;
    const int tid = threadIdx.x;
    __shared__ float sa[HD*HD];
    const float* ap = attn + ((long)(b*HEADS + h)) * HD * HD;
    for (int i = tid; i < HD*HD; i += 256) sa[i] = ap[i];
    __syncthreads();
    const int o = blockIdx.x * 4 + (tid >> 6);
    const int d = tid & 63;
    const float* wrow = w_out + (long)o * DIM + h * HD;
    float acc = 0.f;
#pragma unroll
    for (int c = 0; c < HD; c++) acc += wrow[c] * sa[c*HD + d];
    W2h[((long)b*DIM + o) * DIM + h*HD + d] = __float2half_rn(acc);
}

// ---------------- launcher ----------------
extern "C" void kernel_launch(void* const* d_in, const int* in_sizes, int n_in,
                              void* d_out, int out_size)
{
    const float* x    = (const float*)d_in[0];
    const float* y    = (const float*)d_in[1];
    const float* temp = (const float*)d_in[2];
    const float* wkv  = (const float*)d_in[3];
    const float* wq   = (const float*)d_in[4];
    const float* wdw  = (const float*)d_in[5];
    const float* wout = (const float*)d_in[6];
    float* out = (float*)d_out;

    float *part, *ns2, *attn;
    __half *qh, *kh, *xTh, *yTh, *vTh, *wkvh, *wqTh, *wdwh, *wc2h, *w2h;
    cudaGetSymbolAddress((void**)&part, g_part);
    cudaGetSymbolAddress((void**)&ns2,  g_ns2);
    cudaGetSymbolAddress((void**)&attn, g_attn);
    cudaGetSymbolAddress((void**)&qh,   g_qh);
    cudaGetSymbolAddress((void**)&kh,   g_kh);
    cudaGetSymbolAddress((void**)&xTh,  g_xTh);
    cudaGetSymbolAddress((void**)&yTh,  g_yTh);
    cudaGetSymbolAddress((void**)&vTh,  g_vTh);
    cudaGetSymbolAddress((void**)&wkvh, g_wkvh);
    cudaGetSymbolAddress((void**)&wqTh, g_wqTh);
    cudaGetSymbolAddress((void**)&wdwh, g_wdwh);
    cudaGetSymbolAddress((void**)&wc2h, g_wc2h);
    cudaGetSymbolAddress((void**)&w2h,  g_w2h);

    cudaFuncSetAttribute(hgemm<0,0>, cudaFuncAttributeMaxDynamicSharedMemorySize, SMEMB);
    cudaFuncSetAttribute(hgemm<0,1>, cudaFuncAttributeMaxDynamicSharedMemorySize, SMEMB);
    cudaFuncSetAttribute(hgemm<0,2>, cudaFuncAttributeMaxDynamicSharedMemorySize, SMEMB);
    cudaFuncSetAttribute(hgemm<1,1>, cudaFuncAttributeMaxDynamicSharedMemorySize, SMEMB);
    cudaFuncSetAttribute(attn_mma2, cudaFuncAttributeMaxDynamicSharedMemorySize, ASMEM);

    // ---- kv hgemm kept at launch #4 (the slot ncu captures) ----
    transpose_h<0><<<dim3(128,16,BATCH), 256>>>(x, (long)DIM*MLEN, xTh,
                                                (long)MLEN*DIM, DIM, MLEN);    // 1
    conv_h<<<2048, 256>>>(wkv, wkvh, 2*DIM*DIM);                               // 2
    prep_wdw_h<<<512, 256>>>(wdw, wdwh);                                       // 3
    hgemm<0,2><<<dim3(32,8,BATCH), 256, SMEMB>>>(
        wkvh, 0L, xTh, (long)MLEN*DIM, kh, (long)DIM*MLEN, MLEN,
        2*DIM, DIM, vTh);                                                      // 4 <- profiled
    transpose_h<0><<<dim3(16,16,1), 256>>>(wq, 0L, wqTh, 0L, DIM, DIM);        // 5
    ypad_zero_h<<<dim3(260,BATCH), 256>>>(yTh);                                // 6
    transpose_h<1><<<dim3(128,16,BATCH), 256>>>(y, (long)DIM*MLEN, yTh,
                                                (long)YROWS*DIM, DIM, MLEN);   // 7
    hgemm<0,1><<<dim3(4,4,9), 256, SMEMB>>>(
        wdwh, (long)DIM*DIM, wqTh, 0L, wc2h, 512L, KCONV, DIM, DIM, nullptr);  // 8
    hgemm<1,1><<<dim3(32,4,BATCH), 256, SMEMB>>>(
        wc2h, 0L, yTh, (long)YROWS*DIM, qh, (long)DIM*MLEN, MLEN,
        DIM, KCONV, nullptr);                                                  // 9
    nsq_kernel<<<512, 256>>>(qh, kh, ns2);                                     // 10
    attn_mma2<<<dim3(8,HEADS,BATCH), 256, ASMEM>>>(qh, kh, part);              // 11
    softmax_kernel<<<BATCH*HEADS*HD, 32>>>(part, ns2, temp, attn);             // 12
    w2_kernel_h<<<dim3(128,HEADS,BATCH), 256>>>(wout, attn, w2h);              // 13
    hgemm<0,0><<<dim3(32,4,BATCH), 256, SMEMB>>>(
        w2h, (long)DIM*DIM, vTh, (long)MLEN*DIM, out, (long)DIM*MLEN, MLEN,
        DIM, DIM, nullptr);                                                    // 14
}

// round 17
// speedup vs baseline: 1.1912x; 1.0295x over previous
#include <cuda_runtime.h>
#include <cuda_fp16.h>
#include <math.h>
#include <stdint.h>

#define BATCH 4
#define DIM   512
#define MLEN  4096
#define HEADS 8
#define HD    64
#define KCONV 4608
#define YROWS 4356
#define SMEMB 61440   // 3 * (10240 + 10240)
#define ASMEM 30720   // attn: 3 * (5120 + 5120)

// ---------------- static scratch ----------------
__device__ float  g_part[BATCH*HEADS*8*HD*HD];
__device__ float  g_ns2 [BATCH*2*DIM];
__device__ float  g_attn[BATCH*HEADS*HD*HD];
__device__ __half g_qh  [BATCH*DIM*MLEN];
__device__ __half g_kh  [BATCH*DIM*MLEN];
__device__ __half g_xTh [BATCH*MLEN*DIM];
__device__ __half g_yTh [BATCH*YROWS*DIM];
__device__ __half g_vTh [BATCH*MLEN*DIM];
__device__ __half g_wkvh[2*DIM*DIM];
__device__ __half g_wqTh[DIM*DIM];
__device__ __half g_wdwh[9*DIM*DIM];
__device__ __half g_wc2h[DIM*KCONV];
__device__ __half g_w2h [BATCH*DIM*DIM];

// ---------------- helpers ----------------
__device__ __forceinline__ void cpa16(uint32_t d, const void* s){
    asm volatile("cp.async.cg.shared.global [%0], [%1], 16;" :: "r"(d), "l"(s));
}
#define CP_COMMIT() asm volatile("cp.async.commit_group;")
#define CP_WAIT1()  asm volatile("cp.async.wait_group 1;")

__device__ __forceinline__ void mma16(float& c0, float& c1, float& c2, float& c3,
                                      uint32_t a0, uint32_t a1, uint32_t a2, uint32_t a3,
                                      uint32_t b0, uint32_t b1){
    asm volatile(
        "mma.sync.aligned.m16n8k16.row.col.f32.f16.f16.f32 "
        "{%0,%1,%2,%3}, {%4,%5,%6,%7}, {%8,%9}, {%0,%1,%2,%3};"
        : "+f"(c0), "+f"(c1), "+f"(c2), "+f"(c3)
        : "r"(a0), "r"(a1), "r"(a2), "r"(a3), "r"(b0), "r"(b1));
}
__device__ __forceinline__ void ldsm4(uint32_t& r0, uint32_t& r1, uint32_t& r2, uint32_t& r3,
                                      uint32_t a){
    asm volatile("ldmatrix.sync.aligned.m8n8.x4.shared.b16 {%0,%1,%2,%3}, [%4];"
        : "=r"(r0), "=r"(r1), "=r"(r2), "=r"(r3) : "r"(a));
}

// ============ hgemm: 128x128, BK=32, 3-stage, occ 2 (validated) ============
// OUTM: 0 fp32 C; 1 fp16 C; 2 kv-special (bm<512 -> fp16 k; else vT fp16)
template<int CONV, int OUTM>
__global__ __launch_bounds__(256, 2)
void hgemm(const __half* __restrict__ A, long lA,
           const __half* __restrict__ B, long lB,
           void* __restrict__ Cv, long lC, int ldC,
           int M, int K, __half* __restrict__ VT)
{
    extern __shared__ __half sh[];
    const uint32_t smb = (uint32_t)__cvta_generic_to_shared(sh);
    A += (long)blockIdx.z * lA;
    B += (long)blockIdx.z * lB;
    const int bm = blockIdx.y * 128, bn = blockIdx.x * 128;
    const int tid = threadIdx.x, lane = tid & 31, warp = tid >> 5;
    const int wm = (warp >> 2) * 64, wn = (warp & 3) * 32;
    const int g = lane >> 2, t = lane & 3;
    const int lrow = tid >> 1, lco = (tid & 1) * 16;

    int ph = 0, pw = 0;
    if (CONV) { const int n = bn + lrow; ph = n >> 6; pw = n & 63; }

    const uint32_t aOff = (uint32_t)((wm + (lane & 15)) * 80 + (lane >> 4) * 16);
    const uint32_t bOff = 10240u + (uint32_t)((wn + (lane & 7) + ((lane >> 4) << 3)) * 80
                                              + ((lane >> 3) & 1) * 16);

    float acc[4][4][4];
#pragma unroll
    for (int i = 0; i < 4; i++)
#pragma unroll
        for (int j = 0; j < 4; j++)
#pragma unroll
            for (int r = 0; r < 4; r++) acc[i][j][r] = 0.f;

    const int T = K >> 5;

    auto load = [&](int s, int tt){
        const int k0 = tt << 5;
        const uint32_t sb = smb + (uint32_t)s * 20480u;
        const __half* asrc = A + (long)(bm + lrow) * K + k0 + lco;
        const uint32_t adst = sb + (uint32_t)lrow * 80u + (uint32_t)lco * 2u;
        cpa16(adst,       asrc);
        cpa16(adst + 16u, asrc + 8);
        const __half* bsrc;
        if (CONV) {
            const int r = k0 >> 9;
            const int dyr = r / 3, dxr = r - 3 * dyr;
            bsrc = B + ((long)((ph + dyr) * 66 + pw + dxr)) * DIM + (k0 & 511) + lco;
        } else {
            bsrc = B + (long)(bn + lrow) * K + k0 + lco;
        }
        const uint32_t bdst = sb + 10240u + (uint32_t)lrow * 80u + (uint32_t)lco * 2u;
        cpa16(bdst,       bsrc);
        cpa16(bdst + 16u, bsrc + 8);
    };

    load(0, 0); CP_COMMIT();
    load(1, 1); CP_COMMIT();

    for (int tt = 0; tt < T; tt++) {
        const int s = tt % 3;
        CP_WAIT1();
        __syncthreads();
        if (tt + 2 < T) load((tt + 2) % 3, tt + 2);
        CP_COMMIT();

        const uint32_t sb = smb + (uint32_t)s * 20480u;
#pragma unroll
        for (int ks = 0; ks < 2; ks++) {
            const uint32_t kb = (uint32_t)ks * 32u;
            uint32_t af[4][4], bf[2][4];
            ldsm4(bf[0][0], bf[0][1], bf[0][2], bf[0][3], sb + bOff + kb);
            ldsm4(bf[1][0], bf[1][1], bf[1][2], bf[1][3], sb + bOff + 1280u + kb);
#pragma unroll
            for (int mi = 0; mi < 4; mi++)
                ldsm4(af[mi][0], af[mi][1], af[mi][2], af[mi][3],
                      sb + aOff + (uint32_t)mi * 1280u + kb);
#pragma unroll
            for (int mi = 0; mi < 4; mi++)
#pragma unroll
                for (int ni = 0; ni < 4; ni++) {
                    const int p = ni >> 1, q2 = (ni & 1) * 2;
                    mma16(acc[mi][ni][0], acc[mi][ni][1], acc[mi][ni][2], acc[mi][ni][3],
                          af[mi][0], af[mi][1], af[mi][2], af[mi][3],
                          bf[p][q2], bf[p][q2 + 1]);
                }
        }
    }

    const bool vpath = (OUTM == 2) && (bm >= 512);
    if (OUTM == 1 || (OUTM == 2 && !vpath)) {
        __half* C = (__half*)Cv + (long)blockIdx.z * lC;
#pragma unroll
        for (int mi = 0; mi < 4; mi++) {
            const int row0 = bm + wm + mi * 16 + g;
#pragma unroll
            for (int ni = 0; ni < 4; ni++) {
                const int col = bn + wn + ni * 8 + 2 * t;
                *(__half2*)(C + (long)row0 * ldC + col) =
                    __floats2half2_rn(acc[mi][ni][0], acc[mi][ni][1]);
                *(__half2*)(C + (long)(row0 + 8) * ldC + col) =
                    __floats2half2_rn(acc[mi][ni][2], acc[mi][ni][3]);
            }
        }
    } else if (OUTM == 0) {
        float* C = (float*)Cv + (long)blockIdx.z * lC;
#pragma unroll
        for (int mi = 0; mi < 4; mi++) {
            const int row0 = bm + wm + mi * 16 + g;
#pragma unroll
            for (int ni = 0; ni < 4; ni++) {
                const int col = bn + wn + ni * 8 + 2 * t;
                *(float2*)(C + (long)row0 * ldC + col) =
                    make_float2(acc[mi][ni][0], acc[mi][ni][1]);
                *(float2*)(C + (long)(row0 + 8) * ldC + col) =
                    make_float2(acc[mi][ni][2], acc[mi][ni][3]);
            }
        }
    } else {
        __syncthreads();
#pragma unroll
        for (int mi = 0; mi < 4; mi++) {
            const int r0 = wm + mi * 16 + g;
#pragma unroll
            for (int ni = 0; ni < 4; ni++) {
                const int c0 = wn + ni * 8 + 2 * t;
                sh[(c0    ) * 136 + r0    ] = __float2half_rn(acc[mi][ni][0]);
                sh[(c0 + 1) * 136 + r0    ] = __float2half_rn(acc[mi][ni][1]);
                sh[(c0    ) * 136 + r0 + 8] = __float2half_rn(acc[mi][ni][2]);
                sh[(c0 + 1) * 136 + r0 + 8] = __float2half_rn(acc[mi][ni][3]);
            }
        }
        __syncthreads();
        __half* vt = VT + (long)blockIdx.z * MLEN * DIM;
        const int ml = tid >> 1, ho = (tid & 1) * 64;
        __half* dst = vt + (long)(bn + ml) * DIM + (bm - 512) + ho;
        const __half* srcp = sh + ml * 136 + ho;
#pragma unroll
        for (int i = 0; i < 8; i++)
            *(uint4*)(dst + i * 8) = *(const uint4*)(srcp + i * 8);
    }
}

// ============ attn_mma2: logits on HMMA (validated, 3-stage) ============
__global__ __launch_bounds__(256, 2)
void attn_mma2(const __half* __restrict__ qh, const __half* __restrict__ kh,
               float* __restrict__ part)
{
    extern __shared__ __half sh[];
    const uint32_t smb = (uint32_t)__cvta_generic_to_shared(sh);
    const int mc = blockIdx.x, h = blockIdx.y, b = blockIdx.z;
    const __half* Qp = qh + ((long)(b * DIM + h * HD)) * MLEN + mc * 512;
    const __half* Kp = kh + ((long)(b * DIM + h * HD)) * MLEN + mc * 512;
    const int tid = threadIdx.x, lane = tid & 31, warp = tid >> 5;
    const int wm = (warp >> 1) * 16, wn = (warp & 1) * 32;
    const int g = lane >> 2, t = lane & 3;
    const int lrow = tid >> 2, lco = (tid & 3) * 8;

    const uint32_t aOff = (uint32_t)((wm + (lane & 15)) * 80 + (lane >> 4) * 16);
    const uint32_t bOff = 5120u + (uint32_t)((wn + (lane & 7) + ((lane >> 4) << 3)) * 80
                                             + ((lane >> 3) & 1) * 16);

    float acc[4][4];
#pragma unroll
    for (int j = 0; j < 4; j++)
#pragma unroll
        for (int r = 0; r < 4; r++) acc[j][r] = 0.f;

    const int T = 16;

    auto load = [&](int s, int tt){
        const int k0 = tt << 5;
        const uint32_t sb = smb + (uint32_t)s * 10240u;
        cpa16(sb + (uint32_t)lrow * 80u + (uint32_t)lco * 2u,
              Qp + (long)lrow * MLEN + k0 + lco);
        cpa16(sb + 5120u + (uint32_t)lrow * 80u + (uint32_t)lco * 2u,
              Kp + (long)lrow * MLEN + k0 + lco);
    };

    load(0, 0); CP_COMMIT();
    load(1, 1); CP_COMMIT();

    for (int tt = 0; tt < T; tt++) {
        const int s = tt % 3;
        CP_WAIT1();
        __syncthreads();
        if (tt + 2 < T) load((tt + 2) % 3, tt + 2);
        CP_COMMIT();

        const uint32_t sb = smb + (uint32_t)s * 10240u;
#pragma unroll
        for (int ks = 0; ks < 2; ks++) {
            const uint32_t kb = (uint32_t)ks * 32u;
            uint32_t af[4], bf[2][4];
            ldsm4(bf[0][0], bf[0][1], bf[0][2], bf[0][3], sb + bOff + kb);
            ldsm4(bf[1][0], bf[1][1], bf[1][2], bf[1][3], sb + bOff + 1280u + kb);
            ldsm4(af[0], af[1], af[2], af[3], sb + aOff + kb);
#pragma unroll
            for (int ni = 0; ni < 4; ni++) {
                const int p = ni >> 1, q2 = (ni & 1) * 2;
                mma16(acc[ni][0], acc[ni][1], acc[ni][2], acc[ni][3],
                      af[0], af[1], af[2], af[3],
                      bf[p][q2], bf[p][q2 + 1]);
            }
        }
    }

    float* pp = part + (((long)(b * HEADS + h)) * 8 + mc) * 4096;
    const int row0 = wm + g;
#pragma unroll
    for (int ni = 0; ni < 4; ni++) {
        const int col = wn + ni * 8 + 2 * t;
        *(float2*)(pp + row0 * 64 + col)       = make_float2(acc[ni][0], acc[ni][1]);
        *(float2*)(pp + (row0 + 8) * 64 + col) = make_float2(acc[ni][2], acc[ni][3]);
    }
}

// ============ row sumsq over fp16 q/k ============
__global__ void nsq_kernel(const __half* __restrict__ qh, const __half* __restrict__ kh,
                           float* __restrict__ ns2)
{
    const int w = threadIdx.x >> 5, lane = threadIdx.x & 31;
    const int gid = blockIdx.x * 8 + w;
    const int isK = gid >= BATCH * DIM;
    const int r = gid & (BATCH * DIM - 1);
    const int b = r >> 9, o = r & 511;
    const __half* src = (isK ? kh : qh) + ((long)(b * DIM + o)) * MLEN;
    float ss = 0.f;
#pragma unroll
    for (int i = 0; i < 16; i++) {
        uint4 v = *(const uint4*)(src + i * 256 + lane * 8);
        const __half2* h2 = (const __half2*)&v;
#pragma unroll
        for (int j = 0; j < 4; j++) {
            float2 f = __half22float2(h2[j]);
            ss += f.x * f.x + f.y * f.y;
        }
    }
#pragma unroll
    for (int o2 = 16; o2; o2 >>= 1) ss += __shfl_xor_sync(~0u, ss, o2);
    if (lane == 0) ns2[b * 1024 + isK * 512 + o] = ss;
}

// ---------------- prep / transpose kernels ----------------
__global__ void conv_h(const float* __restrict__ s, __half* __restrict__ d, int n){
    const int i = blockIdx.x * 256 + threadIdx.x;
    if (i < n) d[i] = __float2half_rn(s[i]);
}

template<int PADY>
__global__ void transpose_h(const float* __restrict__ S, long lS,
                            __half* __restrict__ D, long lD, int R, int C)
{
    __shared__ float tle[32][33];
    S += (long)blockIdx.z * lS;
    D += (long)blockIdx.z * lD;
    const int m0 = blockIdx.x * 32, c0 = blockIdx.y * 32;
    const int tx = threadIdx.x & 31, ty = threadIdx.x >> 5;
#pragma unroll
    for (int i = ty; i < 32; i += 8)
        tle[i][tx] = S[(long)(c0 + i) * C + m0 + tx];
    __syncthreads();
    const long prow = PADY ? (long)(m0 + 2 * (m0 >> 6) + 67) : (long)m0;
#pragma unroll
    for (int i = ty; i < 32; i += 8)
        D[(prow + i) * R + c0 + tx] = __float2half_rn(tle[tx][i]);
}

__global__ void ypad_zero_h(__half* __restrict__ yT)
{
    const int idx = blockIdx.x;
    int row;
    if (idx < 66) row = idx;
    else if (idx < 132) row = 65 * 66 + (idx - 66);
    else { const int i = idx - 132; row = (1 + (i >> 1)) * 66 + (i & 1) * 65; }
    uint32_t* p = (uint32_t*)(yT + ((long)blockIdx.y * YROWS + row) * DIM);
    p[threadIdx.x] = 0u;
}

__global__ void prep_wdw_h(const float* __restrict__ wdw, __half* __restrict__ wdwh)
{
    __shared__ float s[KCONV];
    const int o2 = blockIdx.x;
    const float* src = wdw + (long)o2 * KCONV;
    for (int i = threadIdx.x; i < KCONV; i += 256) s[i] = src[i];
    __syncthreads();
    for (int i = threadIdx.x; i < KCONV; i += 256) {
        const int r = i >> 9, o = i & 511;
        wdwh[((long)r * DIM + o2) * DIM + o] = __float2half_rn(s[o * 9 + r]);
    }
}

__global__ void softmax_kernel(const float* __restrict__ part, const float* __restrict__ ns2,
                               const float* __restrict__ temp, float* __restrict__ attn)
{
    const int row = blockIdx.x;
    const int b = row >> 9, h = (row >> 6) & 7, c = row & 63;
    const int lane = threadIdx.x;
    const float sqs = ns2[b * 1024 + h * HD + c];
    const float sk0 = ns2[b * 1024 + 512 + h * HD + lane];
    const float sk1 = ns2[b * 1024 + 512 + h * HD + lane + 32];
    const float rq  = 1.f / fmaxf(sqrtf(sqs), 1e-12f);
    const float rk0 = 1.f / fmaxf(sqrtf(sk0), 1e-12f);
    const float rk1 = 1.f / fmaxf(sqrtf(sk1), 1e-12f);
    const float tq = rq * temp[h];
    const long base = (((long)(b*HEADS + h)) * 8) * (HD*HD) + c*HD;
    float s0 = 0.f, s1 = 0.f;
#pragma unroll
    for (int mc = 0; mc < 8; mc++) {
        s0 += part[base + (long)mc*(HD*HD) + lane];
        s1 += part[base + (long)mc*(HD*HD) + lane + 32];
    }
    float v0 = s0 * tq * rk0, v1 = s1 * tq * rk1;
    float mx = fmaxf(v0, v1);
#pragma unroll
    for (int o = 16; o; o >>= 1) mx = fmaxf(mx, __shfl_xor_sync(~0u, mx, o));
    const float e0 = expf(v0 - mx), e1 = expf(v1 - mx);
    float s = e0 + e1;
#pragma unroll
    for (int o = 16; o; o >>= 1) s += __shfl_xor_sync(~0u, s, o);
    const float inv = 1.f / s;
    float* ap = attn + (((long)(b*HEADS + h))*HD + c)*HD;
    ap[lane] = e0 * inv;
    ap[lane + 32] = e1 * inv;
}

__global__ void w2_kernel_h(const float* __restrict__ w_out, const float* __restrict__ attn,
                            __half* __restrict__ W2h)
{
    const int b = blockIdx.z, h = blockIdx.y;
    const int tid = threadIdx.x;
    __shared__ float sa[HD*HD];
    const float* ap = attn + ((long)(b*HEADS + h)) * HD * HD;
    for (int i = tid; i < HD*HD; i += 256) sa[i] = ap[i];
    __syncthreads();
    const int o = blockIdx.x * 4 + (tid >> 6);
    const int d = tid & 63;
    const float* wrow = w_out + (long)o * DIM + h * HD;
    float acc = 0.f;
#pragma unroll
    for (int c = 0; c < HD; c++) acc += wrow[c] * sa[c*HD + d];
    W2h[((long)b*DIM + o) * DIM + h*HD + d] = __float2half_rn(acc);
}

// ---------------- launcher: fork x-chain / y-chain onto two streams --------
extern "C" void kernel_launch(void* const* d_in, const int* in_sizes, int n_in,
                              void* d_out, int out_size)
{
    const float* x    = (const float*)d_in[0];
    const float* y    = (const float*)d_in[1];
    const float* temp = (const float*)d_in[2];
    const float* wkv  = (const float*)d_in[3];
    const float* wq   = (const float*)d_in[4];
    const float* wdw  = (const float*)d_in[5];
    const float* wout = (const float*)d_in[6];
    float* out = (float*)d_out;

    float *part, *ns2, *attn;
    __half *qh, *kh, *xTh, *yTh, *vTh, *wkvh, *wqTh, *wdwh, *wc2h, *w2h;
    cudaGetSymbolAddress((void**)&part, g_part);
    cudaGetSymbolAddress((void**)&ns2,  g_ns2);
    cudaGetSymbolAddress((void**)&attn, g_attn);
    cudaGetSymbolAddress((void**)&qh,   g_qh);
    cudaGetSymbolAddress((void**)&kh,   g_kh);
    cudaGetSymbolAddress((void**)&xTh,  g_xTh);
    cudaGetSymbolAddress((void**)&yTh,  g_yTh);
    cudaGetSymbolAddress((void**)&vTh,  g_vTh);
    cudaGetSymbolAddress((void**)&wkvh, g_wkvh);
    cudaGetSymbolAddress((void**)&wqTh, g_wqTh);
    cudaGetSymbolAddress((void**)&wdwh, g_wdwh);
    cudaGetSymbolAddress((void**)&wc2h, g_wc2h);
    cudaGetSymbolAddress((void**)&w2h,  g_w2h);

    cudaFuncSetAttribute(hgemm<0,0>, cudaFuncAttributeMaxDynamicSharedMemorySize, SMEMB);
    cudaFuncSetAttribute(hgemm<0,1>, cudaFuncAttributeMaxDynamicSharedMemorySize, SMEMB);
    cudaFuncSetAttribute(hgemm<0,2>, cudaFuncAttributeMaxDynamicSharedMemorySize, SMEMB);
    cudaFuncSetAttribute(hgemm<1,1>, cudaFuncAttributeMaxDynamicSharedMemorySize, SMEMB);
    cudaFuncSetAttribute(attn_mma2, cudaFuncAttributeMaxDynamicSharedMemorySize, ASMEM);

    // Fork a second stream into the capture (event fork/join; no allocations).
    cudaStream_t s2;
    cudaStreamCreate(&s2);
    cudaEvent_t eFork, eJoin;
    cudaEventCreateWithFlags(&eFork, cudaEventDisableTiming);
    cudaEventCreateWithFlags(&eJoin, cudaEventDisableTiming);

    cudaEventRecord(eFork, 0);
    cudaStreamWaitEvent(s2, eFork, 0);

    // ---- stream 0: x-chain (xT -> wkv convert -> kv GEMM) ----
    transpose_h<0><<<dim3(128,16,BATCH), 256>>>(x, (long)DIM*MLEN, xTh,
                                                (long)MLEN*DIM, DIM, MLEN);
    conv_h<<<2048, 256>>>(wkv, wkvh, 2*DIM*DIM);
    hgemm<0,2><<<dim3(32,8,BATCH), 256, SMEMB>>>(
        wkvh, 0L, xTh, (long)MLEN*DIM, kh, (long)DIM*MLEN, MLEN,
        2*DIM, DIM, vTh);

    // ---- stream s2: y-chain (wdw prep -> wqT -> ypad -> yT -> wc2 -> conv) ----
    prep_wdw_h<<<512, 256, 0, s2>>>(wdw, wdwh);
    transpose_h<0><<<dim3(16,16,1), 256, 0, s2>>>(wq, 0L, wqTh, 0L, DIM, DIM);
    ypad_zero_h<<<dim3(260,BATCH), 256, 0, s2>>>(yTh);
    transpose_h<1><<<dim3(128,16,BATCH), 256, 0, s2>>>(y, (long)DIM*MLEN, yTh,
                                                       (long)YROWS*DIM, DIM, MLEN);
    hgemm<0,1><<<dim3(4,4,9), 256, SMEMB, s2>>>(
        wdwh, (long)DIM*DIM, wqTh, 0L, wc2h, 512L, KCONV, DIM, DIM, nullptr);
    hgemm<1,1><<<dim3(32,4,BATCH), 256, SMEMB, s2>>>(
        wc2h, 0L, yTh, (long)YROWS*DIM, qh, (long)DIM*MLEN, MLEN,
        DIM, KCONV, nullptr);

    cudaEventRecord(eJoin, s2);
    cudaStreamWaitEvent(0, eJoin, 0);

    // ---- joined tail on stream 0 ----
    nsq_kernel<<<512, 256>>>(qh, kh, ns2);
    attn_mma2<<<dim3(8,HEADS,BATCH), 256, ASMEM>>>(qh, kh, part);
    softmax_kernel<<<BATCH*HEADS*HD, 32>>>(part, ns2, temp, attn);
    w2_kernel_h<<<dim3(128,HEADS,BATCH), 256>>>(wout, attn, w2h);
    hgemm<0,0><<<dim3(32,4,BATCH), 256, SMEMB>>>(
        w2h, (long)DIM*DIM, vTh, (long)MLEN*DIM, out, (long)DIM*MLEN, MLEN,
        DIM, DIM, nullptr);
}